// round 3
// baseline (speedup 1.0000x reference)
#include <cuda_runtime.h>
#include <math.h>

#define NN_ 50000
#define EE_ 600000
#define CC_ 128
#define LL_ 3
#define GG_ 384   // 3*C
#define HID_ 32
#define NCLS_ 7

// ---------------- device scratch (static; no allocations allowed) ----------------
__device__ float d_m[NN_ * CC_];
__device__ float d_agg[NN_ * CC_];
__device__ float d_h0[NN_ * CC_];
__device__ float d_h1[NN_ * CC_];
__device__ float d_gx[NN_ * GG_];
__device__ float d_gh[NN_ * GG_];
__device__ float d_y0[NN_ * HID_];
__device__ float d_y1[NN_ * HID_];
__device__ int   d_counts[NN_];
__device__ int   d_rowptr[NN_ + 1];
__device__ int   d_cursor[NN_];
__device__ int   d_csr_src[EE_];
__device__ float d_csr_w[EE_];
__device__ int   d_csr_eid[EE_];

// Scratch buffer IDs (resolved device-side; keeps kernel_launch API-free)
#define BUF_M   0
#define BUF_AGG 1
#define BUF_H0  2
#define BUF_H1  3
#define BUF_GX  4
#define BUF_GH  5
#define BUF_Y0  6
#define BUF_Y1  7

__device__ __forceinline__ float* buf_ptr(int id) {
    switch (id) {
        case BUF_M:   return d_m;
        case BUF_AGG: return d_agg;
        case BUF_H0:  return d_h0;
        case BUF_H1:  return d_h1;
        case BUF_GX:  return d_gx;
        case BUF_GH:  return d_gh;
        case BUF_Y0:  return d_y0;
        default:      return d_y1;
    }
}

// ---------------- CSR build ----------------
__global__ void zero_counts_kernel() {
    int i = blockIdx.x * blockDim.x + threadIdx.x;
    if (i < NN_) d_counts[i] = 0;
}

__global__ void hist_kernel(const int* __restrict__ ei) {
    int e = blockIdx.x * blockDim.x + threadIdx.x;
    if (e < EE_) {
        int dst = ei[EE_ + e];
        atomicAdd(&d_counts[dst], 1);
    }
}

__global__ void scan_kernel() {
    __shared__ int part[1024];
    const int CH = (NN_ + 1023) / 1024;
    int t = threadIdx.x;
    int start = t * CH;
    int end = start + CH; if (end > NN_) end = NN_;
    int s = 0;
    for (int i = start; i < end; i++) s += d_counts[i];
    part[t] = s;
    __syncthreads();
    if (t == 0) {
        int acc = 0;
        for (int i = 0; i < 1024; i++) { int v = part[i]; part[i] = acc; acc += v; }
        d_rowptr[NN_] = acc;
    }
    __syncthreads();
    int acc = part[t];
    for (int i = start; i < end; i++) { d_rowptr[i] = acc; acc += d_counts[i]; }
}

__global__ void copy_cursor_kernel() {
    int i = blockIdx.x * blockDim.x + threadIdx.x;
    if (i < NN_) d_cursor[i] = d_rowptr[i];
}

__global__ void scatter_kernel(const int* __restrict__ ei, const float* __restrict__ ew) {
    int e = blockIdx.x * blockDim.x + threadIdx.x;
    if (e < EE_) {
        int src = ei[e];
        int dst = ei[EE_ + e];
        int pos = atomicAdd(&d_cursor[dst], 1);
        d_csr_src[pos] = src;
        d_csr_w[pos]   = ew[e];
        d_csr_eid[pos] = e;
    }
}

// per-node insertion sort by original edge id -> deterministic summation order
__global__ void sort_segments_kernel() {
    int n = blockIdx.x * blockDim.x + threadIdx.x;
    if (n >= NN_) return;
    int lo = d_rowptr[n], hi = d_rowptr[n + 1];
    for (int i = lo + 1; i < hi; i++) {
        int ke = d_csr_eid[i]; int ks = d_csr_src[i]; float kw = d_csr_w[i];
        int j = i - 1;
        while (j >= lo && d_csr_eid[j] > ke) {
            d_csr_eid[j + 1] = d_csr_eid[j];
            d_csr_src[j + 1] = d_csr_src[j];
            d_csr_w[j + 1]   = d_csr_w[j];
            j--;
        }
        d_csr_eid[j + 1] = ke; d_csr_src[j + 1] = ks; d_csr_w[j + 1] = kw;
    }
}

// ---------------- copy x -> h0 ----------------
__global__ void copy_x_kernel(const float* __restrict__ src) {
    int i = blockIdx.x * blockDim.x + threadIdx.x;
    if (i < NN_ * CC_ / 4) {
        reinterpret_cast<float4*>(d_h0)[i] = reinterpret_cast<const float4*>(src)[i];
    }
}

// ---------------- tiled SGEMM: C[Nr,Mc] = A[Nr,K] * B (+bias, opt tanh) ----------------
// TRANSB=0: B is [K,Mc] (NN).  TRANSB=1: B is [Mc,K] (NT, i.e. A @ B^T).
// Aid/Cid >= 0 select device scratch buffers; Aext used when Aid < 0.
template <int TRANSB, int ACT>
__global__ void __launch_bounds__(256)
sgemm_kernel(const float* __restrict__ Aext, int Aid,
             const float* __restrict__ B, const float* __restrict__ bias,
             float* __restrict__ Cext, int Cid,
             int Nr, int Mc, int K) {
    const float* A = (Aid >= 0) ? buf_ptr(Aid) : Aext;
    float* Cout    = (Cid >= 0) ? buf_ptr(Cid) : Cext;

    const int BM = 64, BN = 64, BK = 32;
    __shared__ __align__(16) float As[BK][BM + 4];  // [kk][row]
    __shared__ __align__(16) float Bs[BK][BN];      // [kk][col]

    int tid = threadIdx.x;           // 256 threads
    int tx = tid % 16, ty = tid / 16;
    int row0 = blockIdx.y * BM, col0 = blockIdx.x * BN;

    float acc[4][4];
#pragma unroll
    for (int i = 0; i < 4; i++)
#pragma unroll
        for (int j = 0; j < 4; j++) acc[i][j] = 0.f;

    for (int k0 = 0; k0 < K; k0 += BK) {
        // load A tile 64x32 -> As[kk][row]
        {
            int r  = tid / 8;          // 0..31
            int c4 = (tid % 8) * 4;    // 0..28
#pragma unroll
            for (int rr = r; rr < BM; rr += 32) {
                int grow = row0 + rr;
                float4 v = make_float4(0.f, 0.f, 0.f, 0.f);
                if (grow < Nr)
                    v = *reinterpret_cast<const float4*>(A + (size_t)grow * K + k0 + c4);
                As[c4 + 0][rr] = v.x; As[c4 + 1][rr] = v.y;
                As[c4 + 2][rr] = v.z; As[c4 + 3][rr] = v.w;
            }
        }
        // load B tile -> Bs[kk][col]
        if (TRANSB) {
            int c  = tid / 8;          // 0..31
            int k4 = (tid % 8) * 4;    // 0..28
#pragma unroll
            for (int cc = c; cc < BN; cc += 32) {
                int gcol = col0 + cc;
                float4 v = make_float4(0.f, 0.f, 0.f, 0.f);
                if (gcol < Mc)
                    v = *reinterpret_cast<const float4*>(B + (size_t)gcol * K + k0 + k4);
                Bs[k4 + 0][cc] = v.x; Bs[k4 + 1][cc] = v.y;
                Bs[k4 + 2][cc] = v.z; Bs[k4 + 3][cc] = v.w;
            }
        } else {
            int kk = tid / 16;         // 0..15
            int c4 = (tid % 16) * 4;   // 0..60
#pragma unroll
            for (int k2 = kk; k2 < BK; k2 += 16) {
                int gc = col0 + c4;
                float4 v = make_float4(0.f, 0.f, 0.f, 0.f);
                if (gc < Mc)
                    v = *reinterpret_cast<const float4*>(B + (size_t)(k0 + k2) * Mc + gc);
                *reinterpret_cast<float4*>(&Bs[k2][c4]) = v;
            }
        }
        __syncthreads();

#pragma unroll
        for (int kk = 0; kk < BK; kk++) {
            float4 av = *reinterpret_cast<const float4*>(&As[kk][ty * 4]);
            float4 bv = *reinterpret_cast<const float4*>(&Bs[kk][tx * 4]);
            float a[4] = {av.x, av.y, av.z, av.w};
            float b[4] = {bv.x, bv.y, bv.z, bv.w};
#pragma unroll
            for (int i = 0; i < 4; i++)
#pragma unroll
                for (int j = 0; j < 4; j++) acc[i][j] += a[i] * b[j];
        }
        __syncthreads();
    }

#pragma unroll
    for (int i = 0; i < 4; i++) {
        int gr = row0 + ty * 4 + i;
        if (gr >= Nr) continue;
#pragma unroll
        for (int j = 0; j < 4; j++) {
            int gc = col0 + tx * 4 + j;
            if (gc >= Mc) continue;
            float v = acc[i][j];
            if (bias) v += bias[gc];
            if (ACT)  v = tanhf(v);
            Cout[(size_t)gr * Mc + gc] = v;
        }
    }
}

// ---------------- aggregation: one warp per node (reads d_m, writes d_agg) ----------------
__global__ void aggregate_kernel() {
    int gw = (blockIdx.x * blockDim.x + threadIdx.x) >> 5;
    int lane = threadIdx.x & 31;
    if (gw >= NN_) return;
    int lo = d_rowptr[gw], hi = d_rowptr[gw + 1];
    float4 acc = make_float4(0.f, 0.f, 0.f, 0.f);
    for (int e = lo; e < hi; e++) {
        int s = 0; float w = 0.f;
        if (lane == 0) { s = d_csr_src[e]; w = d_csr_w[e]; }
        s = __shfl_sync(0xFFFFFFFFu, s, 0);
        w = __shfl_sync(0xFFFFFFFFu, w, 0);
        float4 v = *reinterpret_cast<const float4*>(d_m + (size_t)s * CC_ + lane * 4);
        acc.x += w * v.x; acc.y += w * v.y; acc.z += w * v.z; acc.w += w * v.w;
    }
    *reinterpret_cast<float4*>(d_agg + (size_t)gw * CC_ + lane * 4) = acc;
}

// ---------------- GRU gates (reads d_gx, d_gh, h[hin]; writes h[hout]) ----------------
__global__ void gru_gate_kernel(int hin_id, int hout_id) {
    const float* hin = buf_ptr(hin_id);
    float* hout = buf_ptr(hout_id);
    int idx = blockIdx.x * blockDim.x + threadIdx.x;
    if (idx >= NN_ * CC_) return;
    int node = idx >> 7;       // /128
    int c    = idx & 127;
    size_t base = (size_t)node * GG_ + c;
    float xr = d_gx[base], xz = d_gx[base + CC_], xn = d_gx[base + 2 * CC_];
    float hr = d_gh[base], hz = d_gh[base + CC_], hn = d_gh[base + 2 * CC_];
    float r = 1.f / (1.f + expf(-(xr + hr)));
    float z = 1.f / (1.f + expf(-(xz + hz)));
    float nn = tanhf(xn + r * hn);
    hout[idx] = (1.f - z) * nn + z * hin[idx];
}

// ---------------- head: logits + log_softmax (reads d_y0) ----------------
__global__ void head_kernel(const float* __restrict__ w3,
                            const float* __restrict__ b3, float* __restrict__ out) {
    __shared__ float sw[NCLS_ * HID_];
    __shared__ float sb[NCLS_];
    int t = threadIdx.x;
    for (int i = t; i < NCLS_ * HID_; i += blockDim.x) sw[i] = w3[i];
    if (t < NCLS_) sb[t] = b3[t];
    __syncthreads();
    int n = blockIdx.x * blockDim.x + t;
    if (n >= NN_) return;
    float yv[HID_];
#pragma unroll
    for (int k4 = 0; k4 < HID_; k4 += 4) {
        float4 v = *reinterpret_cast<const float4*>(d_y0 + (size_t)n * HID_ + k4);
        yv[k4] = v.x; yv[k4 + 1] = v.y; yv[k4 + 2] = v.z; yv[k4 + 3] = v.w;
    }
    float logit[NCLS_];
    float mx = -1e30f;
#pragma unroll
    for (int c = 0; c < NCLS_; c++) {
        float s = sb[c];
#pragma unroll
        for (int k = 0; k < HID_; k++) s += yv[k] * sw[c * HID_ + k];
        logit[c] = s;
        mx = fmaxf(mx, s);
    }
    float se = 0.f;
#pragma unroll
    for (int c = 0; c < NCLS_; c++) se += expf(logit[c] - mx);
    float lse = logf(se) + mx;
#pragma unroll
    for (int c = 0; c < NCLS_; c++) out[(size_t)n * NCLS_ + c] = logit[c] - lse;
}

// ---------------- host: kernel launches ONLY ----------------
extern "C" void kernel_launch(void* const* d_in, const int* in_sizes, int n_in,
                              void* d_out, int out_size) {
    const float* x    = (const float*)d_in[0];
    const int*   ei   = (const int*)  d_in[1];
    const float* ew   = (const float*)d_in[2];
    const float* cw   = (const float*)d_in[3];
    const float* w_ih = (const float*)d_in[4];
    const float* w_hh = (const float*)d_in[5];
    const float* b_ih = (const float*)d_in[6];
    const float* b_hh = (const float*)d_in[7];
    const float* w0   = (const float*)d_in[8];
    const float* b0   = (const float*)d_in[9];
    const float* w1   = (const float*)d_in[10];
    const float* b1   = (const float*)d_in[11];
    const float* w2   = (const float*)d_in[12];
    const float* b2   = (const float*)d_in[13];
    const float* w3   = (const float*)d_in[14];
    const float* b3   = (const float*)d_in[15];
    float* out = (float*)d_out;

    // ---- CSR build (deterministic via per-segment eid sort) ----
    zero_counts_kernel<<<(NN_ + 255) / 256, 256>>>();
    hist_kernel<<<(EE_ + 255) / 256, 256>>>(ei);
    scan_kernel<<<1, 1024>>>();
    copy_cursor_kernel<<<(NN_ + 255) / 256, 256>>>();
    scatter_kernel<<<(EE_ + 255) / 256, 256>>>(ei, ew);
    sort_segments_kernel<<<(NN_ + 255) / 256, 256>>>();

    // h0 = x
    copy_x_kernel<<<(NN_ * CC_ / 4 + 255) / 256, 256>>>(x);

    dim3 blk(256);
    dim3 grid_conv((CC_ + 63) / 64, (NN_ + 63) / 64);
    dim3 grid_gru ((GG_ + 63) / 64, (NN_ + 63) / 64);

    int hcur = BUF_H0, hnext = BUF_H1;
    for (int l = 0; l < LL_; l++) {
        // m = h @ W[l]          (NN)
        sgemm_kernel<0, 0><<<grid_conv, blk>>>(nullptr, hcur, cw + (size_t)l * CC_ * CC_,
                                               nullptr, nullptr, BUF_M, NN_, CC_, CC_);
        // agg = segment_sum(w * m[src])
        aggregate_kernel<<<(NN_ * 32 + 255) / 256, 256>>>();
        // gx = agg @ w_ih^T + b_ih ; gh = h @ w_hh^T + b_hh   (NT)
        sgemm_kernel<1, 0><<<grid_gru, blk>>>(nullptr, BUF_AGG, w_ih, b_ih,
                                              nullptr, BUF_GX, NN_, GG_, CC_);
        sgemm_kernel<1, 0><<<grid_gru, blk>>>(nullptr, hcur, w_hh, b_hh,
                                              nullptr, BUF_GH, NN_, GG_, CC_);
        // gates
        gru_gate_kernel<<<(NN_ * CC_ + 255) / 256, 256>>>(hcur, hnext);
        int t = hcur; hcur = hnext; hnext = t;
    }

    // MLP: y0 = tanh(h w0^T + b0); y1 = tanh(y0 w1^T + b1); y0 = tanh(y1 w2^T + b2)
    dim3 grid_m0((HID_ + 63) / 64, (NN_ + 63) / 64);
    sgemm_kernel<1, 1><<<grid_m0, blk>>>(nullptr, hcur,   w0, b0, nullptr, BUF_Y0, NN_, HID_, CC_);
    sgemm_kernel<1, 1><<<grid_m0, blk>>>(nullptr, BUF_Y0, w1, b1, nullptr, BUF_Y1, NN_, HID_, HID_);
    sgemm_kernel<1, 1><<<grid_m0, blk>>>(nullptr, BUF_Y1, w2, b2, nullptr, BUF_Y0, NN_, HID_, HID_);
    head_kernel<<<(NN_ + 127) / 128, 128>>>(w3, b3, out);
}

// round 5
// speedup vs baseline: 1.4506x; 1.4506x over previous
#include <cuda_runtime.h>
#include <cuda_bf16.h>
#include <mma.h>
#include <math.h>
#include <stdint.h>

using namespace nvcuda;

#define NN_ 50000
#define EE_ 600000
#define CC_ 128
#define LL_ 3
#define GG_ 384   // 3*C
#define HID_ 32
#define NCLS_ 7

// ======================= device scratch =======================
__device__ float d_m[NN_ * CC_];
__device__ float d_h0[NN_ * CC_];
__device__ float d_h1[NN_ * CC_];
__device__ float d_gx[NN_ * GG_];
__device__ float d_gh[NN_ * GG_];
__device__ float d_y0[NN_ * HID_];
__device__ float d_y1[NN_ * HID_];
// bf16 splits (raw ushort)
__device__ unsigned short d_hsp_hi[NN_ * CC_];
__device__ unsigned short d_hsp_lo[NN_ * CC_];
__device__ unsigned short d_agg_hi[NN_ * CC_];
__device__ unsigned short d_agg_lo[NN_ * CC_];
__device__ unsigned short d_cwt_hi[LL_ * CC_ * CC_];  // transposed conv weight [j][k]
__device__ unsigned short d_cwt_lo[LL_ * CC_ * CC_];
__device__ unsigned short d_wih_hi[GG_ * CC_];
__device__ unsigned short d_wih_lo[GG_ * CC_];
__device__ unsigned short d_whh_hi[GG_ * CC_];
__device__ unsigned short d_whh_lo[GG_ * CC_];
// CSR
__device__ int   d_counts[NN_];
__device__ int   d_rowptr[NN_ + 1];
__device__ int   d_cursor[NN_];
__device__ int   d_csr_src[EE_];
__device__ float d_csr_w[EE_];
__device__ int   d_csr_eid[EE_];

#define BUF_H0  2
#define BUF_H1  3
#define BUF_Y0  6
#define BUF_Y1  7
__device__ __forceinline__ float* buf_ptr(int id) {
    switch (id) {
        case BUF_H0: return d_h0;
        case BUF_H1: return d_h1;
        case BUF_Y0: return d_y0;
        default:     return d_y1;
    }
}

__device__ __forceinline__ void split2(float v, unsigned short& hi, unsigned short& lo) {
    __nv_bfloat16 h = __float2bfloat16(v);
    float r = v - __bfloat162float(h);
    __nv_bfloat16 l = __float2bfloat16(r);
    hi = __bfloat16_as_ushort(h);
    lo = __bfloat16_as_ushort(l);
}

// ======================= kernel 0: weight splits + zero counts =======================
#define R_CWT (LL_ * CC_ * CC_)      // 49152
#define R_W   (GG_ * CC_)            // 49152
__global__ void init_kernel(const float* __restrict__ cw, const float* __restrict__ w_ih,
                            const float* __restrict__ w_hh) {
    int idx = blockIdx.x * blockDim.x + threadIdx.x;
    if (idx < R_CWT) {
        int l = idx / (CC_ * CC_);
        int r = idx % (CC_ * CC_);
        int j = r / CC_, k = r % CC_;
        split2(cw[l * CC_ * CC_ + k * CC_ + j], d_cwt_hi[idx], d_cwt_lo[idx]);
        return;
    }
    idx -= R_CWT;
    if (idx < R_W) { split2(w_ih[idx], d_wih_hi[idx], d_wih_lo[idx]); return; }
    idx -= R_W;
    if (idx < R_W) { split2(w_hh[idx], d_whh_hi[idx], d_whh_lo[idx]); return; }
    idx -= R_W;
    if (idx < NN_) d_counts[idx] = 0;
}

// ======================= CSR build =======================
__global__ void hist_kernel(const int* __restrict__ ei) {
    int e = blockIdx.x * blockDim.x + threadIdx.x;
    if (e < EE_) atomicAdd(&d_counts[ei[EE_ + e]], 1);
}

__global__ void scan_kernel() {
    __shared__ int part[1024];
    const int CH = (NN_ + 1023) / 1024;
    int t = threadIdx.x;
    int start = t * CH;
    int end = start + CH; if (end > NN_) end = NN_;
    int s = 0;
    for (int i = start; i < end; i++) s += d_counts[i];
    part[t] = s;
    __syncthreads();
    if (t == 0) {
        int acc = 0;
        for (int i = 0; i < 1024; i++) { int v = part[i]; part[i] = acc; acc += v; }
        d_rowptr[NN_] = acc;
    }
    __syncthreads();
    int acc = part[t];
    for (int i = start; i < end; i++) {
        d_rowptr[i] = acc; d_cursor[i] = acc; acc += d_counts[i];
    }
}

__global__ void scatter_kernel(const int* __restrict__ ei, const float* __restrict__ ew) {
    int e = blockIdx.x * blockDim.x + threadIdx.x;
    if (e < EE_) {
        int src = ei[e];
        int dst = ei[EE_ + e];
        int pos = atomicAdd(&d_cursor[dst], 1);
        d_csr_src[pos] = src;
        d_csr_w[pos]   = ew[e];
        d_csr_eid[pos] = e;
    }
}

// sort segments (deterministic order) + split x -> hsp
#define XSPLIT4 (NN_ * CC_ / 4)
__global__ void sortsplit_kernel(const float* __restrict__ x) {
    int gid = blockIdx.x * blockDim.x + threadIdx.x;
    if (gid < NN_) {
        int lo = d_rowptr[gid], hi = d_rowptr[gid + 1];
        for (int i = lo + 1; i < hi; i++) {
            int ke = d_csr_eid[i]; int ks = d_csr_src[i]; float kw = d_csr_w[i];
            int j = i - 1;
            while (j >= lo && d_csr_eid[j] > ke) {
                d_csr_eid[j + 1] = d_csr_eid[j];
                d_csr_src[j + 1] = d_csr_src[j];
                d_csr_w[j + 1]   = d_csr_w[j];
                j--;
            }
            d_csr_eid[j + 1] = ke; d_csr_src[j + 1] = ks; d_csr_w[j + 1] = kw;
        }
        return;
    }
    int t = gid - NN_;
    if (t < XSPLIT4) {
        float4 v = reinterpret_cast<const float4*>(x)[t];
        ushort4 h, l;
        split2(v.x, h.x, l.x); split2(v.y, h.y, l.y);
        split2(v.z, h.z, l.z); split2(v.w, h.w, l.w);
        reinterpret_cast<ushort4*>(d_hsp_hi)[t] = h;
        reinterpret_cast<ushort4*>(d_hsp_lo)[t] = l;
    }
}

// ======================= wmma GEMM: C[NN_,Mc] = A @ B^T (+bias) =======================
// A: bf16 hi/lo [NN_,128] K-major.  B: bf16 hi/lo [Mc,128] K-major (NT).
// 3-term split: C = Ahi*Bhi + Ahi*Blo + Alo*Bhi, fp32 accum.
// CTA: 256 thr, 128x128 tile. Warp (4 rows x 2 cols): 32x64 = 2x4 m16n16k16 frags.
#define TS 40          // smem tile k-stride (bf16 elems), mult of 8
#define TILE_B (128 * TS)             // elems per tile
#define EPI_S 132                     // epilogue float stride
#define DSMEM_BYTES (128 * EPI_S * 4) // 67584 > 4*TILE_B*2 = 40960

__global__ void __launch_bounds__(256, 1)
wmma_gemm_kernel(int a_id, int b_id, int out_id, const float* __restrict__ bias, int Mc) {
    extern __shared__ char smem[];
    __nv_bfloat16* sAhi = reinterpret_cast<__nv_bfloat16*>(smem);
    __nv_bfloat16* sAlo = sAhi + TILE_B;
    __nv_bfloat16* sBhi = sAlo + TILE_B;
    __nv_bfloat16* sBlo = sBhi + TILE_B;
    float* sC = reinterpret_cast<float*>(smem);

    const unsigned short *Ahi, *Alo, *Bhi, *Blo;
    if (a_id == 0) { Ahi = d_hsp_hi; Alo = d_hsp_lo; }
    else           { Ahi = d_agg_hi; Alo = d_agg_lo; }
    if (b_id <= 2) { Bhi = d_cwt_hi + b_id * CC_ * CC_; Blo = d_cwt_lo + b_id * CC_ * CC_; }
    else if (b_id == 3) { Bhi = d_wih_hi; Blo = d_wih_lo; }
    else                { Bhi = d_whh_hi; Blo = d_whh_lo; }
    float* C = (out_id == 0) ? d_m : (out_id == 1 ? d_gx : d_gh);

    int tid = threadIdx.x, wid = tid >> 5;
    int warp_m = wid >> 1;       // 0..3 -> 32-row band
    int warp_n = wid & 1;        // 0..1 -> 64-col band
    int row0 = blockIdx.y * 128, col0 = blockIdx.x * 128;

    wmma::fragment<wmma::accumulator, 16, 16, 16, float> acc[2][4];
#pragma unroll
    for (int i = 0; i < 2; i++)
#pragma unroll
        for (int j = 0; j < 4; j++) wmma::fill_fragment(acc[i][j], 0.f);

    for (int k0 = 0; k0 < CC_; k0 += 32) {
        __syncthreads();
        // load A hi/lo: 128 rows x 32 k -> 512 uint4 per tile; 2 per thread
#pragma unroll
        for (int t = 0; t < 2; t++) {
            int v = tid + t * 256;
            int r = v >> 2;                 // 0..127
            int c8 = (v & 3) << 3;          // 0,8,16,24
            int grow = row0 + r;
            uint4 vh = make_uint4(0u, 0u, 0u, 0u), vl = vh;
            if (grow < NN_) {
                size_t g = (size_t)grow * CC_ + k0 + c8;
                vh = *reinterpret_cast<const uint4*>(Ahi + g);
                vl = *reinterpret_cast<const uint4*>(Alo + g);
            }
            *reinterpret_cast<uint4*>(sAhi + r * TS + c8) = vh;
            *reinterpret_cast<uint4*>(sAlo + r * TS + c8) = vl;
        }
        // load B hi/lo (cols always in range: Mc multiple of 128)
#pragma unroll
        for (int t = 0; t < 2; t++) {
            int v = tid + t * 256;
            int r = v >> 2;
            int c8 = (v & 3) << 3;
            size_t g = (size_t)(col0 + r) * CC_ + k0 + c8;
            *reinterpret_cast<uint4*>(sBhi + r * TS + c8) =
                *reinterpret_cast<const uint4*>(Bhi + g);
            *reinterpret_cast<uint4*>(sBlo + r * TS + c8) =
                *reinterpret_cast<const uint4*>(Blo + g);
        }
        __syncthreads();

#pragma unroll
        for (int ks = 0; ks < 2; ks++) {
            wmma::fragment<wmma::matrix_a, 16, 16, 16, __nv_bfloat16, wmma::row_major> fahi[2], falo[2];
            wmma::fragment<wmma::matrix_b, 16, 16, 16, __nv_bfloat16, wmma::col_major> fbhi[4], fblo[4];
#pragma unroll
            for (int i = 0; i < 2; i++) {
                const __nv_bfloat16* pa = sAhi + (warp_m * 32 + i * 16) * TS + ks * 16;
                wmma::load_matrix_sync(fahi[i], pa, TS);
                wmma::load_matrix_sync(falo[i], sAlo + (pa - sAhi), TS);
            }
#pragma unroll
            for (int j = 0; j < 4; j++) {
                const __nv_bfloat16* pb = sBhi + (warp_n * 64 + j * 16) * TS + ks * 16;
                wmma::load_matrix_sync(fbhi[j], pb, TS);
                wmma::load_matrix_sync(fblo[j], sBlo + (pb - sBhi), TS);
            }
#pragma unroll
            for (int i = 0; i < 2; i++)
#pragma unroll
                for (int j = 0; j < 4; j++) {
                    wmma::mma_sync(acc[i][j], fahi[i], fbhi[j], acc[i][j]);
                    wmma::mma_sync(acc[i][j], fahi[i], fblo[j], acc[i][j]);
                    wmma::mma_sync(acc[i][j], falo[i], fbhi[j], acc[i][j]);
                }
        }
    }

    // epilogue: stage to smem, then guarded bias-fused stores
    __syncthreads();
#pragma unroll
    for (int i = 0; i < 2; i++)
#pragma unroll
        for (int j = 0; j < 4; j++) {
            float* p = sC + (warp_m * 32 + i * 16) * EPI_S + warp_n * 64 + j * 16;
            wmma::store_matrix_sync(p, acc[i][j], EPI_S, wmma::mem_row_major);
        }
    __syncthreads();

#pragma unroll
    for (int t = 0; t < 16; t++) {
        int v = tid + t * 256;        // 4096 float4 total
        int r = v >> 5;               // 0..127
        int c4 = (v & 31) << 2;       // 0..124
        int grow = row0 + r;
        if (grow >= NN_) continue;
        float4 o;
        o.x = sC[r * EPI_S + c4 + 0];
        o.y = sC[r * EPI_S + c4 + 1];
        o.z = sC[r * EPI_S + c4 + 2];
        o.w = sC[r * EPI_S + c4 + 3];
        if (bias) {
            int bc = col0 + c4;
            o.x += bias[bc]; o.y += bias[bc + 1]; o.z += bias[bc + 2]; o.w += bias[bc + 3];
        }
        *reinterpret_cast<float4*>(C + (size_t)grow * Mc + col0 + c4) = o;
    }
}

// ======================= aggregation: warp per node -> bf16 split =======================
__global__ void aggregate_kernel() {
    int gw = (blockIdx.x * blockDim.x + threadIdx.x) >> 5;
    int lane = threadIdx.x & 31;
    if (gw >= NN_) return;
    int lo = d_rowptr[gw], hi = d_rowptr[gw + 1];
    float4 acc = make_float4(0.f, 0.f, 0.f, 0.f);
    for (int e = lo; e < hi; e++) {
        int s = 0; float w = 0.f;
        if (lane == 0) { s = d_csr_src[e]; w = d_csr_w[e]; }
        s = __shfl_sync(0xFFFFFFFFu, s, 0);
        w = __shfl_sync(0xFFFFFFFFu, w, 0);
        float4 v = *reinterpret_cast<const float4*>(d_m + (size_t)s * CC_ + lane * 4);
        acc.x += w * v.x; acc.y += w * v.y; acc.z += w * v.z; acc.w += w * v.w;
    }
    ushort4 h, l;
    split2(acc.x, h.x, l.x); split2(acc.y, h.y, l.y);
    split2(acc.z, h.z, l.z); split2(acc.w, h.w, l.w);
    size_t o = ((size_t)gw * CC_ + lane * 4) / 4;
    reinterpret_cast<ushort4*>(d_agg_hi)[o] = h;
    reinterpret_cast<ushort4*>(d_agg_lo)[o] = l;
}

// ======================= GRU gates + split of new h =======================
__global__ void gru_gate_kernel(const float* __restrict__ hin_ext, int hin_id, int hout_id) {
    const float* hin = (hin_id >= 0) ? buf_ptr(hin_id) : hin_ext;
    float* hout = buf_ptr(hout_id);
    int idx = blockIdx.x * blockDim.x + threadIdx.x;
    if (idx >= NN_ * CC_) return;
    int node = idx >> 7;
    int c    = idx & 127;
    size_t base = (size_t)node * GG_ + c;
    float xr = d_gx[base], xz = d_gx[base + CC_], xn = d_gx[base + 2 * CC_];
    float hr = d_gh[base], hz = d_gh[base + CC_], hn = d_gh[base + 2 * CC_];
    float r = 1.f / (1.f + expf(-(xr + hr)));
    float z = 1.f / (1.f + expf(-(xz + hz)));
    float nn = tanhf(xn + r * hn);
    float hv = (1.f - z) * nn + z * hin[idx];
    hout[idx] = hv;
    split2(hv, d_hsp_hi[idx], d_hsp_lo[idx]);
}

// ======================= small SIMT GEMM (MLP): C = A @ B^T + bias, tanh =======================
template <int ACT>
__global__ void __launch_bounds__(256)
sgemm_nt_kernel(int Aid, const float* __restrict__ B, const float* __restrict__ bias,
                int Cid, int Nr, int Mc, int K) {
    const float* A = buf_ptr(Aid);
    float* Cout    = buf_ptr(Cid);
    const int BM = 64, BN = 64, BK = 32;
    __shared__ __align__(16) float As[BK][BM + 4];
    __shared__ __align__(16) float Bs[BK][BN];
    int tid = threadIdx.x;
    int tx = tid % 16, ty = tid / 16;
    int row0 = blockIdx.y * BM, col0 = blockIdx.x * BN;
    float acc[4][4];
#pragma unroll
    for (int i = 0; i < 4; i++)
#pragma unroll
        for (int j = 0; j < 4; j++) acc[i][j] = 0.f;

    for (int k0 = 0; k0 < K; k0 += BK) {
        {
            int r = tid / 8, c4 = (tid % 8) * 4;
#pragma unroll
            for (int rr = r; rr < BM; rr += 32) {
                int grow = row0 + rr;
                float4 v = make_float4(0.f, 0.f, 0.f, 0.f);
                if (grow < Nr)
                    v = *reinterpret_cast<const float4*>(A + (size_t)grow * K + k0 + c4);
                As[c4 + 0][rr] = v.x; As[c4 + 1][rr] = v.y;
                As[c4 + 2][rr] = v.z; As[c4 + 3][rr] = v.w;
            }
        }
        {
            int c = tid / 8, k4 = (tid % 8) * 4;
#pragma unroll
            for (int cc = c; cc < BN; cc += 32) {
                int gcol = col0 + cc;
                float4 v = make_float4(0.f, 0.f, 0.f, 0.f);
                if (gcol < Mc)
                    v = *reinterpret_cast<const float4*>(B + (size_t)gcol * K + k0 + k4);
                Bs[k4 + 0][cc] = v.x; Bs[k4 + 1][cc] = v.y;
                Bs[k4 + 2][cc] = v.z; Bs[k4 + 3][cc] = v.w;
            }
        }
        __syncthreads();
#pragma unroll
        for (int kk = 0; kk < BK; kk++) {
            float4 av = *reinterpret_cast<const float4*>(&As[kk][ty * 4]);
            float4 bv = *reinterpret_cast<const float4*>(&Bs[kk][tx * 4]);
            float a[4] = {av.x, av.y, av.z, av.w};
            float b[4] = {bv.x, bv.y, bv.z, bv.w};
#pragma unroll
            for (int i = 0; i < 4; i++)
#pragma unroll
                for (int j = 0; j < 4; j++) acc[i][j] += a[i] * b[j];
        }
        __syncthreads();
    }
#pragma unroll
    for (int i = 0; i < 4; i++) {
        int gr = row0 + ty * 4 + i;
        if (gr >= Nr) continue;
#pragma unroll
        for (int j = 0; j < 4; j++) {
            int gc = col0 + tx * 4 + j;
            if (gc >= Mc) continue;
            float v = acc[i][j] + bias[gc];
            if (ACT) v = tanhf(v);
            Cout[(size_t)gr * Mc + gc] = v;
        }
    }
}

// ======================= head: logits + log_softmax =======================
__global__ void head_kernel(const float* __restrict__ w3,
                            const float* __restrict__ b3, float* __restrict__ out) {
    __shared__ float sw[NCLS_ * HID_];
    __shared__ float sb[NCLS_];
    int t = threadIdx.x;
    for (int i = t; i < NCLS_ * HID_; i += blockDim.x) sw[i] = w3[i];
    if (t < NCLS_) sb[t] = b3[t];
    __syncthreads();
    int n = blockIdx.x * blockDim.x + t;
    if (n >= NN_) return;
    float yv[HID_];
#pragma unroll
    for (int k4 = 0; k4 < HID_; k4 += 4) {
        float4 v = *reinterpret_cast<const float4*>(d_y0 + (size_t)n * HID_ + k4);
        yv[k4] = v.x; yv[k4 + 1] = v.y; yv[k4 + 2] = v.z; yv[k4 + 3] = v.w;
    }
    float logit[NCLS_];
    float mx = -1e30f;
#pragma unroll
    for (int c = 0; c < NCLS_; c++) {
        float s = sb[c];
#pragma unroll
        for (int k = 0; k < HID_; k++) s += yv[k] * sw[c * HID_ + k];
        logit[c] = s;
        mx = fmaxf(mx, s);
    }
    float se = 0.f;
#pragma unroll
    for (int c = 0; c < NCLS_; c++) se += expf(logit[c] - mx);
    float lse = logf(se) + mx;
#pragma unroll
    for (int c = 0; c < NCLS_; c++) out[(size_t)n * NCLS_ + c] = logit[c] - lse;
}

// ======================= host: kernel launches only =======================
extern "C" void kernel_launch(void* const* d_in, const int* in_sizes, int n_in,
                              void* d_out, int out_size) {
    const float* x    = (const float*)d_in[0];
    const int*   ei   = (const int*)  d_in[1];
    const float* ew   = (const float*)d_in[2];
    const float* cw   = (const float*)d_in[3];
    const float* w_ih = (const float*)d_in[4];
    const float* w_hh = (const float*)d_in[5];
    const float* b_ih = (const float*)d_in[6];
    const float* b_hh = (const float*)d_in[7];
    const float* w0   = (const float*)d_in[8];
    const float* b0   = (const float*)d_in[9];
    const float* w1   = (const float*)d_in[10];
    const float* b1   = (const float*)d_in[11];
    const float* w2   = (const float*)d_in[12];
    const float* b2   = (const float*)d_in[13];
    const float* w3   = (const float*)d_in[14];
    const float* b3   = (const float*)d_in[15];
    float* out = (float*)d_out;

    cudaFuncSetAttribute(wmma_gemm_kernel, cudaFuncAttributeMaxDynamicSharedMemorySize,
                         DSMEM_BYTES);

    // 0: weight splits + zero counts
    {
        int total = R_CWT + 2 * R_W + NN_;
        init_kernel<<<(total + 255) / 256, 256>>>(cw, w_ih, w_hh);
    }
    // CSR build
    hist_kernel<<<(EE_ + 255) / 256, 256>>>(ei);
    scan_kernel<<<1, 1024>>>();
    scatter_kernel<<<(EE_ + 255) / 256, 256>>>(ei, ew);
    sortsplit_kernel<<<(NN_ + XSPLIT4 + 255) / 256, 256>>>(x);

    dim3 grid_conv(1, (NN_ + 127) / 128);
    dim3 grid_gru(GG_ / 128, (NN_ + 127) / 128);

    int hcur = -1;                 // layer0 hin = x (ext)
    int hbuf[2] = {BUF_H0, BUF_H1};
    for (int l = 0; l < LL_; l++) {
        // m = h @ W[l]   (HMMA, bf16 3-term split)
        wmma_gemm_kernel<<<grid_conv, 256, DSMEM_BYTES>>>(0, l, 0, nullptr, CC_);
        // agg = segment_sum(w * m[src])  -> bf16 split
        aggregate_kernel<<<(NN_ * 32 + 255) / 256, 256>>>();
        // gx = agg @ w_ih^T + b_ih ; gh = h @ w_hh^T + b_hh
        wmma_gemm_kernel<<<grid_gru, 256, DSMEM_BYTES>>>(1, 3, 1, b_ih, GG_);
        wmma_gemm_kernel<<<grid_gru, 256, DSMEM_BYTES>>>(0, 4, 2, b_hh, GG_);
        // gates -> h fp32 + bf16 split
        int hout = hbuf[l & 1];
        gru_gate_kernel<<<(NN_ * CC_ + 255) / 256, 256>>>(x, hcur, hout);
        hcur = hout;
    }

    // MLP (SIMT; tiny GEMMs)
    dim3 blk(256);
    dim3 grid_m0(1, (NN_ + 63) / 64);
    sgemm_nt_kernel<1><<<grid_m0, blk>>>(hcur,   w0, b0, BUF_Y0, NN_, HID_, CC_);
    sgemm_nt_kernel<1><<<grid_m0, blk>>>(BUF_Y0, w1, b1, BUF_Y1, NN_, HID_, HID_);
    sgemm_nt_kernel<1><<<grid_m0, blk>>>(BUF_Y1, w2, b2, BUF_Y0, NN_, HID_, HID_);
    head_kernel<<<(NN_ + 127) / 128, 128>>>(w3, b3, out);
}

// round 6
// speedup vs baseline: 1.6372x; 1.1286x over previous
#include <cuda_runtime.h>
#include <cuda_bf16.h>
#include <mma.h>
#include <math.h>
#include <stdint.h>

using namespace nvcuda;

#define NN_ 50000
#define EE_ 600000
#define CC_ 128
#define LL_ 3
#define HID_ 32
#define NCLS_ 7

// ======================= device scratch =======================
__device__ float d_h0[NN_ * CC_];
__device__ float d_h1[NN_ * CC_];
__device__ float d_g[NN_ * 512];          // [rz_sum(256) | xn(128) | hn(128)]
__device__ float d_y0[NN_ * HID_];
__device__ float d_y1[NN_ * HID_];
// bf16 splits (raw ushort)
__device__ unsigned short d_hsp_hi[NN_ * CC_];
__device__ unsigned short d_hsp_lo[NN_ * CC_];
__device__ unsigned short d_agg_hi[NN_ * CC_];
__device__ unsigned short d_agg_lo[NN_ * CC_];
// fused weights: Brz[l][256 cols][256 K] (K<128: cmb, K>=128: whh), Bxn[l][128][128], Bhn[128][128]
__device__ unsigned short d_Brz_hi[LL_ * 256 * 256];
__device__ unsigned short d_Brz_lo[LL_ * 256 * 256];
__device__ unsigned short d_Bxn_hi[LL_ * 128 * 128];
__device__ unsigned short d_Bxn_lo[LL_ * 128 * 128];
__device__ unsigned short d_Bhn_hi[128 * 128];
__device__ unsigned short d_Bhn_lo[128 * 128];
__device__ float d_bias[512];
// CSR
__device__ int   d_counts[NN_];
__device__ int   d_rowptr[NN_ + 1];
__device__ int   d_cursor[NN_];
__device__ int   d_csr_src[EE_];
__device__ float d_csr_w[EE_];
__device__ int   d_csr_eid[EE_];

#define BUF_H0  2
#define BUF_H1  3
#define BUF_Y0  6
#define BUF_Y1  7
__device__ __forceinline__ float* buf_ptr(int id) {
    switch (id) {
        case BUF_H0: return d_h0;
        case BUF_H1: return d_h1;
        case BUF_Y0: return d_y0;
        default:     return d_y1;
    }
}

__device__ __forceinline__ void split2(float v, unsigned short& hi, unsigned short& lo) {
    __nv_bfloat16 h = __float2bfloat16(v);
    float r = v - __bfloat162float(h);
    __nv_bfloat16 l = __float2bfloat16(r);
    hi = __bfloat16_as_ushort(h);
    lo = __bfloat16_as_ushort(l);
}

__device__ __forceinline__ uint32_t smem_u32(const void* p) {
    uint32_t a;
    asm("{ .reg .u64 t; cvta.to.shared.u64 t, %1; cvt.u32.u64 %0, t; }" : "=r"(a) : "l"(p));
    return a;
}
__device__ __forceinline__ void cpa16(uint32_t d, const void* s, int sz) {
    asm volatile("cp.async.ca.shared.global [%0], [%1], 16, %2;\n" :: "r"(d), "l"(s), "r"(sz));
}
#define CP_COMMIT() asm volatile("cp.async.commit_group;\n" ::: "memory")
#define CP_WAIT1()  asm volatile("cp.async.wait_group 1;\n" ::: "memory")
#define CP_WAIT0()  asm volatile("cp.async.wait_group 0;\n" ::: "memory")

// ======================= init: fused weights + biases + counts + x split =======================
#define R_CMB (LL_ * 384 * 128)   // 147456 : cmb[l][j][k] = sum_t W_l[k,t]*wih[j,t]
#define R_WRZ (LL_ * 256 * 128)   // 98304  : Brz k>=128 <- whh
#define R_BHN (128 * 128)         // 16384
#define R_BIAS 512
#define R_XS (NN_ * CC_ / 4)      // 1.6M float4 splits of x

__global__ void init_kernel(const float* __restrict__ cw, const float* __restrict__ wih,
                            const float* __restrict__ whh, const float* __restrict__ bih,
                            const float* __restrict__ bhh, const float* __restrict__ x) {
    int idx = blockIdx.x * blockDim.x + threadIdx.x;
    if (idx < R_CMB) {
        int l = idx / (384 * 128);
        int r = idx % (384 * 128);
        int j = r / 128, k = r % 128;
        const float* Wl = cw + l * CC_ * CC_ + k * CC_;   // W_l[k, t]
        const float* wj = wih + j * CC_;                  // wih[j, t]
        float s = 0.f;
#pragma unroll 8
        for (int t = 0; t < CC_; t++) s += Wl[t] * wj[t];
        if (j < 256) {
            int dst = l * 65536 + j * 256 + k;
            split2(s, d_Brz_hi[dst], d_Brz_lo[dst]);
        } else {
            int dst = l * 16384 + (j - 256) * 128 + k;
            split2(s, d_Bxn_hi[dst], d_Bxn_lo[dst]);
        }
        return;
    }
    idx -= R_CMB;
    if (idx < R_WRZ) {
        int l = idx / (256 * 128);
        int r = idx % (256 * 128);
        int j = r / 128, k = r % 128;
        int dst = l * 65536 + j * 256 + 128 + k;
        split2(whh[j * 128 + k], d_Brz_hi[dst], d_Brz_lo[dst]);
        return;
    }
    idx -= R_WRZ;
    if (idx < R_BHN) {
        int j = idx / 128, k = idx % 128;
        split2(whh[(256 + j) * 128 + k], d_Bhn_hi[idx], d_Bhn_lo[idx]);
        return;
    }
    idx -= R_BHN;
    if (idx < R_BIAS) {
        float b;
        if (idx < 256)      b = bih[idx] + bhh[idx];
        else if (idx < 384) b = bih[idx];            // xn bias
        else                b = bhh[idx - 128];      // hn bias = bhh[256 + (idx-384)]
        d_bias[idx] = b;
        return;
    }
    idx -= R_BIAS;
    if (idx < NN_) { d_counts[idx] = 0; return; }
    idx -= NN_;
    if (idx < R_XS) {
        float4 v = reinterpret_cast<const float4*>(x)[idx];
        ushort4 h, l;
        split2(v.x, h.x, l.x); split2(v.y, h.y, l.y);
        split2(v.z, h.z, l.z); split2(v.w, h.w, l.w);
        reinterpret_cast<ushort4*>(d_hsp_hi)[idx] = h;
        reinterpret_cast<ushort4*>(d_hsp_lo)[idx] = l;
    }
}

// ======================= CSR build =======================
__global__ void hist_kernel(const int* __restrict__ ei) {
    int e = blockIdx.x * blockDim.x + threadIdx.x;
    if (e < EE_) atomicAdd(&d_counts[ei[EE_ + e]], 1);
}

__global__ void scan_kernel() {
    __shared__ int part[1024];
    const int CH = (NN_ + 1023) / 1024;
    int t = threadIdx.x;
    int start = t * CH;
    int end = start + CH; if (end > NN_) end = NN_;
    int s = 0;
    for (int i = start; i < end; i++) s += d_counts[i];
    part[t] = s;
    __syncthreads();
    if (t == 0) {
        int acc = 0;
        for (int i = 0; i < 1024; i++) { int v = part[i]; part[i] = acc; acc += v; }
        d_rowptr[NN_] = acc;
    }
    __syncthreads();
    int acc = part[t];
    for (int i = start; i < end; i++) {
        d_rowptr[i] = acc; d_cursor[i] = acc; acc += d_counts[i];
    }
}

__global__ void scatter_kernel(const int* __restrict__ ei, const float* __restrict__ ew) {
    int e = blockIdx.x * blockDim.x + threadIdx.x;
    if (e < EE_) {
        int src = ei[e];
        int dst = ei[EE_ + e];
        int pos = atomicAdd(&d_cursor[dst], 1);
        d_csr_src[pos] = src;
        d_csr_w[pos]   = ew[e];
        d_csr_eid[pos] = e;
    }
}

// deterministic per-segment order via insertion sort on edge id
__global__ void sort_kernel() {
    int n = blockIdx.x * blockDim.x + threadIdx.x;
    if (n >= NN_) return;
    int lo = d_rowptr[n], hi = d_rowptr[n + 1];
    for (int i = lo + 1; i < hi; i++) {
        int ke = d_csr_eid[i]; int ks = d_csr_src[i]; float kw = d_csr_w[i];
        int j = i - 1;
        while (j >= lo && d_csr_eid[j] > ke) {
            d_csr_eid[j + 1] = d_csr_eid[j];
            d_csr_src[j + 1] = d_csr_src[j];
            d_csr_w[j + 1]   = d_csr_w[j];
            j--;
        }
        d_csr_eid[j + 1] = ke; d_csr_src[j + 1] = ks; d_csr_w[j + 1] = kw;
    }
}

// ======================= aggregation: agg = S * h, warp per node, bf16 split out =======================
__global__ void aggregate_kernel(const float* __restrict__ xext, int h_id) {
    const float* hsrc = (h_id >= 0) ? buf_ptr(h_id) : xext;
    int gw = (blockIdx.x * blockDim.x + threadIdx.x) >> 5;
    int lane = threadIdx.x & 31;
    if (gw >= NN_) return;
    int lo = d_rowptr[gw], hi = d_rowptr[gw + 1];
    float4 acc = make_float4(0.f, 0.f, 0.f, 0.f);
    for (int e = lo; e < hi; e++) {
        int s = 0; float w = 0.f;
        if (lane == 0) { s = d_csr_src[e]; w = d_csr_w[e]; }
        s = __shfl_sync(0xFFFFFFFFu, s, 0);
        w = __shfl_sync(0xFFFFFFFFu, w, 0);
        float4 v = *reinterpret_cast<const float4*>(hsrc + (size_t)s * CC_ + lane * 4);
        acc.x += w * v.x; acc.y += w * v.y; acc.z += w * v.z; acc.w += w * v.w;
    }
    ushort4 h, l;
    split2(acc.x, h.x, l.x); split2(acc.y, h.y, l.y);
    split2(acc.z, h.z, l.z); split2(acc.w, h.w, l.w);
    size_t o = ((size_t)gw * CC_ + lane * 4) / 4;
    reinterpret_cast<ushort4*>(d_agg_hi)[o] = h;
    reinterpret_cast<ushort4*>(d_agg_lo)[o] = l;
}

// ======================= fused GRU GEMM, cp.async double-buffered =======================
// grid (4, 391): bx 0/1: rz-sum, K=256 (A=[agg|h]); bx 2: xn (A=agg); bx 3: hn (A=h).
// Output: d_g[row][512] = [rz(256) | xn(128) | hn(128)], bias fused.
#define TSK 40
#define TILE_E (128 * TSK)          // 5120 elems per tile
#define BUF_E  (4 * TILE_E)         // Ahi,Alo,Bhi,Blo
#define GEMM_SMEM (2 * BUF_E * 2)   // 81920 bytes
#define EPI_S 132

__global__ void __launch_bounds__(256, 1)
gru_gemm_kernel(int layer) {
    extern __shared__ __align__(16) char smem[];
    __nv_bfloat16* s = reinterpret_cast<__nv_bfloat16*>(smem);
    float* sC = reinterpret_cast<float*>(smem);
    uint32_t su = smem_u32(smem);

    int bx = blockIdx.x;
    int row0 = blockIdx.y * 128;
    const unsigned short *A0hi, *A0lo, *A1hi = nullptr, *A1lo = nullptr, *Bhi, *Blo;
    int Kb, outc0;
    if (bx < 2) {
        A0hi = d_agg_hi; A0lo = d_agg_lo; A1hi = d_hsp_hi; A1lo = d_hsp_lo;
        Bhi = d_Brz_hi + layer * 65536 + bx * 128 * 256;
        Blo = d_Brz_lo + layer * 65536 + bx * 128 * 256;
        Kb = 256; outc0 = bx * 128;
    } else if (bx == 2) {
        A0hi = d_agg_hi; A0lo = d_agg_lo;
        Bhi = d_Bxn_hi + layer * 16384; Blo = d_Bxn_lo + layer * 16384;
        Kb = 128; outc0 = 256;
    } else {
        A0hi = d_hsp_hi; A0lo = d_hsp_lo;
        Bhi = d_Bhn_hi; Blo = d_Bhn_lo;
        Kb = 128; outc0 = 384;
    }
    int nck = Kb >> 5;
    int tid = threadIdx.x, wid = tid >> 5;
    int warp_m = wid >> 1, warp_n = wid & 1;

    wmma::fragment<wmma::accumulator, 16, 16, 16, float> acc[2][4];
#pragma unroll
    for (int i = 0; i < 2; i++)
#pragma unroll
        for (int j = 0; j < 4; j++) wmma::fill_fragment(acc[i][j], 0.f);

    auto prefetch = [&](int c, int bsel) {
        int k0 = c * 32;
        const unsigned short* Ah = A0hi;
        const unsigned short* Al = A0lo;
        int koff = k0;
        if (k0 >= 128) { Ah = A1hi; Al = A1lo; koff = k0 - 128; }
        uint32_t sb = su + (uint32_t)bsel * (BUF_E * 2);
#pragma unroll
        for (int t = 0; t < 2; t++) {
            int v = tid + t * 256;
            int r = v >> 2, c8 = (v & 3) << 3;
            uint32_t so = (uint32_t)(r * TSK + c8) * 2;
            int grow = row0 + r;
            int ok = (grow < NN_);
            size_t ga = ok ? ((size_t)grow * CC_ + koff + c8) : 0;
            int sz = ok ? 16 : 0;
            cpa16(sb + so,             Ah + ga, sz);
            cpa16(sb + 10240 + so,     Al + ga, sz);
            size_t gb = (size_t)r * Kb + k0 + c8;
            cpa16(sb + 20480 + so,     Bhi + gb, 16);
            cpa16(sb + 30720 + so,     Blo + gb, 16);
        }
    };

    prefetch(0, 0);
    CP_COMMIT();

    for (int c = 0; c < nck; c++) {
        if (c + 1 < nck) {
            prefetch(c + 1, (c + 1) & 1);
            CP_COMMIT();
            CP_WAIT1();
        } else {
            CP_WAIT0();
        }
        __syncthreads();

        const __nv_bfloat16* sb   = s + (c & 1) * BUF_E;
        const __nv_bfloat16* tAhi = sb;
        const __nv_bfloat16* tAlo = sb + TILE_E;
        const __nv_bfloat16* tBhi = sb + 2 * TILE_E;
        const __nv_bfloat16* tBlo = sb + 3 * TILE_E;

#pragma unroll
        for (int ks = 0; ks < 2; ks++) {
            wmma::fragment<wmma::matrix_a, 16, 16, 16, __nv_bfloat16, wmma::row_major> fahi[2], falo[2];
            wmma::fragment<wmma::matrix_b, 16, 16, 16, __nv_bfloat16, wmma::col_major> fbhi[4], fblo[4];
#pragma unroll
            for (int i = 0; i < 2; i++) {
                int off = (warp_m * 32 + i * 16) * TSK + ks * 16;
                wmma::load_matrix_sync(fahi[i], tAhi + off, TSK);
                wmma::load_matrix_sync(falo[i], tAlo + off, TSK);
            }
#pragma unroll
            for (int j = 0; j < 4; j++) {
                int off = (warp_n * 64 + j * 16) * TSK + ks * 16;
                wmma::load_matrix_sync(fbhi[j], tBhi + off, TSK);
                wmma::load_matrix_sync(fblo[j], tBlo + off, TSK);
            }
#pragma unroll
            for (int i = 0; i < 2; i++)
#pragma unroll
                for (int j = 0; j < 4; j++) {
                    wmma::mma_sync(acc[i][j], fahi[i], fbhi[j], acc[i][j]);
                    wmma::mma_sync(acc[i][j], fahi[i], fblo[j], acc[i][j]);
                    wmma::mma_sync(acc[i][j], falo[i], fbhi[j], acc[i][j]);
                }
        }
        __syncthreads();
    }

    // epilogue via smem
#pragma unroll
    for (int i = 0; i < 2; i++)
#pragma unroll
        for (int j = 0; j < 4; j++) {
            float* p = sC + (warp_m * 32 + i * 16) * EPI_S + warp_n * 64 + j * 16;
            wmma::store_matrix_sync(p, acc[i][j], EPI_S, wmma::mem_row_major);
        }
    __syncthreads();

#pragma unroll
    for (int t = 0; t < 16; t++) {
        int v = tid + t * 256;
        int r = v >> 5;
        int c4 = (v & 31) << 2;
        int grow = row0 + r;
        if (grow >= NN_) continue;
        int gc = outc0 + c4;
        float4 o;
        o.x = sC[r * EPI_S + c4 + 0] + d_bias[gc + 0];
        o.y = sC[r * EPI_S + c4 + 1] + d_bias[gc + 1];
        o.z = sC[r * EPI_S + c4 + 2] + d_bias[gc + 2];
        o.w = sC[r * EPI_S + c4 + 3] + d_bias[gc + 3];
        *reinterpret_cast<float4*>(d_g + (size_t)grow * 512 + gc) = o;
    }
}

// ======================= GRU gate (new layout) + split of new h =======================
__global__ void gate_kernel(const float* __restrict__ xext, int hin_id, int hout_id) {
    const float* hin = (hin_id >= 0) ? buf_ptr(hin_id) : xext;
    float* hout = buf_ptr(hout_id);
    int idx = blockIdx.x * blockDim.x + threadIdx.x;
    if (idx >= NN_ * CC_) return;
    int node = idx >> 7;
    int c    = idx & 127;
    size_t gb = (size_t)node * 512;
    float rz = d_g[gb + c];
    float zz = d_g[gb + 128 + c];
    float xn = d_g[gb + 256 + c];
    float hn = d_g[gb + 384 + c];
    float r = 1.f / (1.f + expf(-rz));
    float z = 1.f / (1.f + expf(-zz));
    float n = tanhf(xn + r * hn);
    float hv = (1.f - z) * n + z * hin[idx];
    hout[idx] = hv;
    split2(hv, d_hsp_hi[idx], d_hsp_lo[idx]);
}

// ======================= small SIMT GEMM (MLP): C = A @ B^T + bias, tanh =======================
template <int ACT>
__global__ void __launch_bounds__(256)
sgemm_nt_kernel(int Aid, const float* __restrict__ B, const float* __restrict__ bias,
                int Cid, int Nr, int Mc, int K) {
    const float* A = buf_ptr(Aid);
    float* Cout    = buf_ptr(Cid);
    const int BM = 64, BN = 64, BK = 32;
    __shared__ __align__(16) float As[BK][BM + 4];
    __shared__ __align__(16) float Bs[BK][BN];
    int tid = threadIdx.x;
    int tx = tid % 16, ty = tid / 16;
    int row0 = blockIdx.y * BM, col0 = blockIdx.x * BN;
    float acc[4][4];
#pragma unroll
    for (int i = 0; i < 4; i++)
#pragma unroll
        for (int j = 0; j < 4; j++) acc[i][j] = 0.f;

    for (int k0 = 0; k0 < K; k0 += BK) {
        {
            int r = tid / 8, c4 = (tid % 8) * 4;
#pragma unroll
            for (int rr = r; rr < BM; rr += 32) {
                int grow = row0 + rr;
                float4 v = make_float4(0.f, 0.f, 0.f, 0.f);
                if (grow < Nr)
                    v = *reinterpret_cast<const float4*>(A + (size_t)grow * K + k0 + c4);
                As[c4 + 0][rr] = v.x; As[c4 + 1][rr] = v.y;
                As[c4 + 2][rr] = v.z; As[c4 + 3][rr] = v.w;
            }
        }
        {
            int c = tid / 8, k4 = (tid % 8) * 4;
#pragma unroll
            for (int cc = c; cc < BN; cc += 32) {
                int gcol = col0 + cc;
                float4 v = make_float4(0.f, 0.f, 0.f, 0.f);
                if (gcol < Mc)
                    v = *reinterpret_cast<const float4*>(B + (size_t)gcol * K + k0 + k4);
                Bs[k4 + 0][cc] = v.x; Bs[k4 + 1][cc] = v.y;
                Bs[k4 + 2][cc] = v.z; Bs[k4 + 3][cc] = v.w;
            }
        }
        __syncthreads();
#pragma unroll
        for (int kk = 0; kk < BK; kk++) {
            float4 av = *reinterpret_cast<const float4*>(&As[kk][ty * 4]);
            float4 bv = *reinterpret_cast<const float4*>(&Bs[kk][tx * 4]);
            float a[4] = {av.x, av.y, av.z, av.w};
            float b[4] = {bv.x, bv.y, bv.z, bv.w};
#pragma unroll
            for (int i = 0; i < 4; i++)
#pragma unroll
                for (int j = 0; j < 4; j++) acc[i][j] += a[i] * b[j];
        }
        __syncthreads();
    }
#pragma unroll
    for (int i = 0; i < 4; i++) {
        int gr = row0 + ty * 4 + i;
        if (gr >= Nr) continue;
#pragma unroll
        for (int j = 0; j < 4; j++) {
            int gc = col0 + tx * 4 + j;
            if (gc >= Mc) continue;
            float v = acc[i][j] + bias[gc];
            if (ACT) v = tanhf(v);
            Cout[(size_t)gr * Mc + gc] = v;
        }
    }
}

// ======================= head: logits + log_softmax =======================
__global__ void head_kernel(const float* __restrict__ w3,
                            const float* __restrict__ b3, float* __restrict__ out) {
    __shared__ float sw[NCLS_ * HID_];
    __shared__ float sb[NCLS_];
    int t = threadIdx.x;
    for (int i = t; i < NCLS_ * HID_; i += blockDim.x) sw[i] = w3[i];
    if (t < NCLS_) sb[t] = b3[t];
    __syncthreads();
    int n = blockIdx.x * blockDim.x + t;
    if (n >= NN_) return;
    float yv[HID_];
#pragma unroll
    for (int k4 = 0; k4 < HID_; k4 += 4) {
        float4 v = *reinterpret_cast<const float4*>(d_y0 + (size_t)n * HID_ + k4);
        yv[k4] = v.x; yv[k4 + 1] = v.y; yv[k4 + 2] = v.z; yv[k4 + 3] = v.w;
    }
    float logit[NCLS_];
    float mx = -1e30f;
#pragma unroll
    for (int c = 0; c < NCLS_; c++) {
        float s = sb[c];
#pragma unroll
        for (int k = 0; k < HID_; k++) s += yv[k] * sw[c * HID_ + k];
        logit[c] = s;
        mx = fmaxf(mx, s);
    }
    float se = 0.f;
#pragma unroll
    for (int c = 0; c < NCLS_; c++) se += expf(logit[c] - mx);
    float lse = logf(se) + mx;
#pragma unroll
    for (int c = 0; c < NCLS_; c++) out[(size_t)n * NCLS_ + c] = logit[c] - lse;
}

// ======================= host: kernel launches only =======================
extern "C" void kernel_launch(void* const* d_in, const int* in_sizes, int n_in,
                              void* d_out, int out_size) {
    const float* x    = (const float*)d_in[0];
    const int*   ei   = (const int*)  d_in[1];
    const float* ew   = (const float*)d_in[2];
    const float* cw   = (const float*)d_in[3];
    const float* w_ih = (const float*)d_in[4];
    const float* w_hh = (const float*)d_in[5];
    const float* b_ih = (const float*)d_in[6];
    const float* b_hh = (const float*)d_in[7];
    const float* w0   = (const float*)d_in[8];
    const float* b0   = (const float*)d_in[9];
    const float* w1   = (const float*)d_in[10];
    const float* b1   = (const float*)d_in[11];
    const float* w2   = (const float*)d_in[12];
    const float* b2   = (const float*)d_in[13];
    const float* w3   = (const float*)d_in[14];
    const float* b3   = (const float*)d_in[15];
    float* out = (float*)d_out;

    cudaFuncSetAttribute(gru_gemm_kernel, cudaFuncAttributeMaxDynamicSharedMemorySize,
                         GEMM_SMEM);

    // init: fused weights, biases, counts, x split
    {
        int total = R_CMB + R_WRZ + R_BHN + R_BIAS + NN_ + R_XS;
        init_kernel<<<(total + 255) / 256, 256>>>(cw, w_ih, w_hh, b_ih, b_hh, x);
    }
    // CSR build
    hist_kernel<<<(EE_ + 255) / 256, 256>>>(ei);
    scan_kernel<<<1, 1024>>>();
    scatter_kernel<<<(EE_ + 255) / 256, 256>>>(ei, ew);
    sort_kernel<<<(NN_ + 255) / 256, 256>>>();

    dim3 grid_g(4, (NN_ + 127) / 128);
    int hcur = -1;
    int hbuf[2] = {BUF_H0, BUF_H1};
    for (int l = 0; l < LL_; l++) {
        // agg = S * h  (h = x at l=0)
        aggregate_kernel<<<(NN_ * 32 + 255) / 256, 256>>>(x, hcur);
        // fused GRU GEMM: rz-sum (K=256 concat), xn, hn
        gru_gemm_kernel<<<grid_g, 256, GEMM_SMEM>>>(l);
        // gates -> h fp32 + bf16 split
        int hout = hbuf[l & 1];
        gate_kernel<<<(NN_ * CC_ + 255) / 256, 256>>>(x, hcur, hout);
        hcur = hout;
    }

    // MLP (SIMT; tiny GEMMs)
    dim3 blk(256);
    dim3 grid_m0(1, (NN_ + 63) / 64);
    sgemm_nt_kernel<1><<<grid_m0, blk>>>(hcur,   w0, b0, BUF_Y0, NN_, HID_, CC_);
    sgemm_nt_kernel<1><<<grid_m0, blk>>>(BUF_Y0, w1, b1, BUF_Y1, NN_, HID_, HID_);
    sgemm_nt_kernel<1><<<grid_m0, blk>>>(BUF_Y1, w2, b2, BUF_Y0, NN_, HID_, HID_);
    head_kernel<<<(NN_ + 127) / 128, 128>>>(w3, b3, out);
}